// round 5
// baseline (speedup 1.0000x reference)
#include <cuda_runtime.h>
#include <cstdint>
#include <cstddef>

#define B_ 4
#define N_ 8192
#define K_ 32
#define C_ 64

#define RS 288   // attn/h row stride in floats (8 pts * 36)
#define PS 36    // per-point column-slot stride in floats

// precomputed linear parts: Ga = Wa_f @ f + b_attn, G1 = W1_f @ f + b1
__device__ float g_Ga[(size_t)B_ * N_ * C_];
__device__ float g_G1[(size_t)B_ * N_ * C_];

// ---------------------------------------------------------------------------
// precompute kernel: 64 points per block, 256 threads
// ---------------------------------------------------------------------------
__global__ void __launch_bounds__(256) precompute_kernel(
    const float* __restrict__ f,
    const float* __restrict__ Wa, const float* __restrict__ ba,
    const float* __restrict__ W1, const float* __restrict__ b1)
{
    __shared__ float4 Wa4[1024];
    __shared__ float4 W14[1024];
    __shared__ float bsa[64], bs1[64];
    const int tid = threadIdx.x;
    const int b = blockIdx.y, n0 = blockIdx.x * 64;

    for (int i = tid; i < 1024; i += 256) {
        int c = i >> 4, j = (i & 15) * 4;
        Wa4[i] = make_float4(Wa[c*67+3+j], Wa[c*67+4+j], Wa[c*67+5+j], Wa[c*67+6+j]);
        W14[i] = make_float4(W1[c*67+3+j], W1[c*67+4+j], W1[c*67+5+j], W1[c*67+6+j]);
    }
    if (tid < 64) { bsa[tid] = ba[tid]; bs1[tid] = b1[tid]; }
    __syncthreads();

    const int nl = tid & 63, c0 = (tid >> 6) * 16;
    const int n = n0 + nl;
    float x[64];
#pragma unroll
    for (int i = 0; i < 64; i++) x[i] = f[((size_t)b * 64 + i) * N_ + n];

    float oA[16], oB[16];
#pragma unroll
    for (int cc = 0; cc < 16; cc++) {
        const int c = c0 + cc;
        float accA = bsa[c], accB = bs1[c];
#pragma unroll
        for (int q = 0; q < 16; q++) {
            float4 w = Wa4[c * 16 + q];
            float4 v = W14[c * 16 + q];
            accA += w.x*x[4*q] + w.y*x[4*q+1] + w.z*x[4*q+2] + w.w*x[4*q+3];
            accB += v.x*x[4*q] + v.y*x[4*q+1] + v.z*x[4*q+2] + v.w*x[4*q+3];
        }
        oA[cc] = accA; oB[cc] = accB;
    }
    float4* dstA = (float4*)(g_Ga + ((size_t)b * N_ + n) * 64 + c0);
    float4* dstB = (float4*)(g_G1 + ((size_t)b * N_ + n) * 64 + c0);
#pragma unroll
    for (int q = 0; q < 4; q++) {
        dstA[q] = make_float4(oA[4*q], oA[4*q+1], oA[4*q+2], oA[4*q+3]);
        dstB[q] = make_float4(oB[4*q], oB[4*q+1], oB[4*q+2], oB[4*q+3]);
    }
}

// ---------------------------------------------------------------------------
// main kernel: 8 points / block, 512 threads (16 warps for latency hiding)
// ---------------------------------------------------------------------------
__global__ void __launch_bounds__(512, 1) lpamlp_main_kernel(
    const float* __restrict__ p, const int* __restrict__ idx,
    const float* __restrict__ f,
    const float* __restrict__ Wa, const float* __restrict__ W1,
    const float* __restrict__ W2, const float* __restrict__ b2,
    const float* __restrict__ Wf1, const float* __restrict__ bf1,
    const float* __restrict__ Wf2, const float* __restrict__ bf2,
    float* __restrict__ out_f2)
{
    extern __shared__ float sm[];
    float*  attn  = sm;                      // 64*288
    float*  hbuf  = attn + 64 * RS;          // 64*288
    float*  W2T   = hbuf + 64 * RS;          // [k][c] 4096
    float*  Wf1T  = W2T + 4096;              // [i][o] 4096
    float*  Wf2T  = Wf1T + 4096;             // [i][o] 4096
    float4* Wap4  = (float4*)(Wf2T + 4096);  // 64
    float4* W1p4  = Wap4 + 64;               // 64
    float*  bias  = (float*)(W1p4 + 64);     // b2 | bf1 | bf2
    float*  fo_sh = bias + 192;              // 8*64
    float*  g1_sh = fo_sh + 512;             // 8*64

    const int tid = threadIdx.x;
    const int b = blockIdx.y, n0 = blockIdx.x * 8;
    const int w = tid >> 5, lane = tid & 31;

    // ---- init: weights into smem ----
    for (int i = tid; i < 4096; i += 512) {
        W2T[(i & 63) * 64 + (i >> 6)] = W2[i];
        int r = i >> 6, c = i & 63;
        Wf1T[c * 64 + r] = Wf1[i];
        Wf2T[c * 64 + r] = Wf2[i];
    }
    if (tid < 64) {
        Wap4[tid] = make_float4(Wa[tid*67], Wa[tid*67+1], Wa[tid*67+2], 0.f);
        W1p4[tid] = make_float4(W1[tid*67], W1[tid*67+1], W1[tid*67+2], 0.f);
        bias[tid]       = b2[tid];
        bias[64 + tid]  = bf1[tid];
        bias[128 + tid] = bf2[tid];
    }
    __syncthreads();

    // ---- phase G: column = tid&255 (pt,k); c-half = tid>>8 ----
    {
        const int col = tid & 255;
        const int sub = tid >> 8;            // 0 or 1
        const int pt = col >> 5, k = col & 31;
        const int n = n0 + pt;
        const int nb = idx[((size_t)b * N_ + n) * K_ + k];
        const float* pj = p + ((size_t)b * N_ + nb) * 3;
        const float* pc = p + ((size_t)b * N_ + n) * 3;
        const float d0 = pj[0] - pc[0], d1 = pj[1] - pc[1], d2 = pj[2] - pc[2];
        const float4* gaR = (const float4*)(g_Ga + ((size_t)b * N_ + nb) * 64) + sub * 8;
        const float4* g1R = (const float4*)(g_G1 + ((size_t)b * N_ + nb) * 64) + sub * 8;
        const int off = pt * PS + k;
        const int cb = sub * 32;
#pragma unroll
        for (int c4 = 0; c4 < 8; c4++) {
            float4 ga = gaR[c4], gh = g1R[c4];
            float gav[4] = {ga.x, ga.y, ga.z, ga.w};
            float ghv[4] = {gh.x, gh.y, gh.z, gh.w};
#pragma unroll
            for (int j = 0; j < 4; j++) {
                const int c = cb + c4 * 4 + j;
                float4 wa = Wap4[c], w1 = W1p4[c];
                attn[c * RS + off] = gav[j] + wa.x*d0 + wa.y*d1 + wa.z*d2;
                hbuf[c * RS + off] = fmaxf(ghv[j] + w1.x*d0 + w1.y*d1 + w1.z*d2, 0.f);
            }
        }
    }
    __syncthreads();

    // ---- phase S: softmax over neighbors, 1 item (c, pt) per thread ----
    {
        const int c = tid >> 3, pt2 = tid & 7;
        float4* row = (float4*)(attn + c * RS + pt2 * PS);
        float4 v[8];
#pragma unroll
        for (int q = 0; q < 8; q++) v[q] = row[q];
        float m = -1e30f;
#pragma unroll
        for (int q = 0; q < 8; q++)
            m = fmaxf(m, fmaxf(fmaxf(v[q].x, v[q].y), fmaxf(v[q].z, v[q].w)));
        float s = 0.f;
#pragma unroll
        for (int q = 0; q < 8; q++) {
            v[q].x = __expf(v[q].x - m); v[q].y = __expf(v[q].y - m);
            v[q].z = __expf(v[q].z - m); v[q].w = __expf(v[q].w - m);
            s += (v[q].x + v[q].y) + (v[q].z + v[q].w);
        }
        const float inv = __fdividef(1.f, s);
#pragma unroll
        for (int q = 0; q < 8; q++) {
            v[q].x *= inv; v[q].y *= inv; v[q].z *= inv; v[q].w *= inv;
            row[q] = v[q];
        }
    }
    __syncthreads();

    // ---- phase M: xi = W2 @ h register-tiled (8 ch x 4 cols / thread) ----
    {
        const int chan0 = (w & 7) * 8;
        const int half = w >> 3;
        const int ptl = lane >> 3, q = lane & 7;
        const int pt = half * 4 + ptl;
        const int colbase = pt * PS + q * 4;
        float acc[8][4];
#pragma unroll
        for (int a = 0; a < 8; a++)
#pragma unroll
            for (int j = 0; j < 4; j++) acc[a][j] = 0.f;

#pragma unroll 4
        for (int k = 0; k < 64; k++) {
            float4 a0 = *(float4*)(W2T + k * 64 + chan0);
            float4 a1 = *(float4*)(W2T + k * 64 + chan0 + 4);
            float4 bv = *(float4*)(hbuf + k * RS + colbase);
            float av[8] = {a0.x, a0.y, a0.z, a0.w, a1.x, a1.y, a1.z, a1.w};
#pragma unroll
            for (int a = 0; a < 8; a++) {
                acc[a][0] += av[a] * bv.x;
                acc[a][1] += av[a] * bv.y;
                acc[a][2] += av[a] * bv.z;
                acc[a][3] += av[a] * bv.w;
            }
        }

#pragma unroll
        for (int a = 0; a < 8; a++) {
            const int c = chan0 + a;
            float4 u = *(float4*)(attn + c * RS + colbase);
            float part = u.x*acc[a][0] + u.y*acc[a][1] + u.z*acc[a][2] + u.w*acc[a][3];
            part += __shfl_xor_sync(0xffffffffu, part, 1);
            part += __shfl_xor_sync(0xffffffffu, part, 2);
            part += __shfl_xor_sync(0xffffffffu, part, 4);
            if (q == 0) {
                const float fr = f[((size_t)b * 64 + c) * N_ + n0 + pt];
                fo_sh[pt * 64 + c] = fmaxf(part + bias[c] + fr, 0.f);
            }
        }
    }
    __syncthreads();

    // ---- phase F: FFN, 1 output channel per thread (2 warps per point) ----
    {
        const int fpt = w >> 1;
        const int c = (w & 1) * 32 + lane;
        float g1 = bias[64 + c];
#pragma unroll
        for (int i = 0; i < 64; i++)
            g1 += fo_sh[fpt * 64 + i] * Wf1T[i * 64 + c];
        g1_sh[fpt * 64 + c] = fmaxf(g1, 0.f);
        __syncthreads();

        float g2 = bias[128 + c];
#pragma unroll
        for (int i = 0; i < 64; i++)
            g2 += g1_sh[fpt * 64 + i] * Wf2T[i * 64 + c];
        out_f2[((size_t)b * 64 + c) * N_ + n0 + fpt] =
            fmaxf(g2 + fo_sh[fpt * 64 + c], 0.f);
    }
}

// ---------------------------------------------------------------------------
// launch
// ---------------------------------------------------------------------------
static const int SMEM_FLOATS = 64*RS + 64*RS + 4096 + 4096 + 4096
                             + 256 + 256 + 192 + 512 + 512;
static const int SMEM_BYTES = SMEM_FLOATS * 4;   // 203,520 B

extern "C" void kernel_launch(void* const* d_in, const int* in_sizes, int n_in,
                              void* d_out, int out_size)
{
    const float* p      = (const float*)d_in[0];
    const float* f      = (const float*)d_in[1];
    const int*   idx    = (const int*)d_in[2];
    const float* W_attn = (const float*)d_in[3];
    const float* b_attn = (const float*)d_in[4];
    const float* W1     = (const float*)d_in[5];
    const float* b1     = (const float*)d_in[6];
    const float* W2     = (const float*)d_in[7];
    const float* b2     = (const float*)d_in[8];
    const float* Wf1    = (const float*)d_in[9];
    const float* bf1    = (const float*)d_in[10];
    const float* Wf2    = (const float*)d_in[11];
    const float* bf2    = (const float*)d_in[12];

    float* out = (float*)d_out;
    const int psz = B_ * N_ * 3;
    const int fsz = B_ * C_ * N_;

    float* out_f2 = out;
    if (out_size >= psz + fsz) {
        cudaMemcpyAsync(out, p, (size_t)psz * sizeof(float),
                        cudaMemcpyDeviceToDevice);
        out_f2 = out + psz;
    }

    precompute_kernel<<<dim3(N_ / 64, B_), 256>>>(f, W_attn, b_attn, W1, b1);

    cudaFuncSetAttribute(lpamlp_main_kernel,
                         cudaFuncAttributeMaxDynamicSharedMemorySize, SMEM_BYTES);
    lpamlp_main_kernel<<<dim3(N_ / 8, B_), 512, SMEM_BYTES>>>(
        p, idx, f, W_attn, W1, W2, b2, Wf1, bf1, Wf2, bf2, out_f2);
}

// round 6
// speedup vs baseline: 1.2082x; 1.2082x over previous
#include <cuda_runtime.h>
#include <cstdint>
#include <cstddef>

#define B_ 4
#define N_ 8192
#define K_ 32
#define C_ 64

#define RS 288   // attn/h row stride in floats (8 pts * 36)
#define PS 36    // per-point column-slot stride in floats

typedef unsigned long long u64;

__device__ __forceinline__ void fma2(u64& d, u64 a, u64 b) {
    asm("fma.rn.f32x2 %0, %1, %2, %0;" : "+l"(d) : "l"(a), "l"(b));
}
__device__ __forceinline__ u64 add2(u64 a, u64 b) {
    u64 r; asm("add.rn.f32x2 %0, %1, %2;" : "=l"(r) : "l"(a), "l"(b)); return r;
}
__device__ __forceinline__ u64 pk2(float lo, float hi) {
    u64 r; asm("mov.b64 %0, {%1, %2};" : "=l"(r) : "f"(lo), "f"(hi)); return r;
}
__device__ __forceinline__ void upk2(float& lo, float& hi, u64 v) {
    asm("mov.b64 {%0, %1}, %2;" : "=f"(lo), "=f"(hi) : "l"(v));
}

// precomputed linear parts: Ga = Wa_f @ f + b_attn, G1 = W1_f @ f + b1
__device__ float g_Ga[(size_t)B_ * N_ * C_];
__device__ float g_G1[(size_t)B_ * N_ * C_];

// ---------------------------------------------------------------------------
// precompute kernel: 64 points per block, 256 threads
// ---------------------------------------------------------------------------
__global__ void __launch_bounds__(256) precompute_kernel(
    const float* __restrict__ f,
    const float* __restrict__ Wa, const float* __restrict__ ba,
    const float* __restrict__ W1, const float* __restrict__ b1)
{
    __shared__ float4 Wa4[1024];
    __shared__ float4 W14[1024];
    __shared__ float bsa[64], bs1[64];
    const int tid = threadIdx.x;
    const int b = blockIdx.y, n0 = blockIdx.x * 64;

    for (int i = tid; i < 1024; i += 256) {
        int c = i >> 4, j = (i & 15) * 4;
        Wa4[i] = make_float4(Wa[c*67+3+j], Wa[c*67+4+j], Wa[c*67+5+j], Wa[c*67+6+j]);
        W14[i] = make_float4(W1[c*67+3+j], W1[c*67+4+j], W1[c*67+5+j], W1[c*67+6+j]);
    }
    if (tid < 64) { bsa[tid] = ba[tid]; bs1[tid] = b1[tid]; }
    __syncthreads();

    const int nl = tid & 63, c0 = (tid >> 6) * 16;
    const int n = n0 + nl;
    float x[64];
#pragma unroll
    for (int i = 0; i < 64; i++) x[i] = f[((size_t)b * 64 + i) * N_ + n];

    float oA[16], oB[16];
#pragma unroll
    for (int cc = 0; cc < 16; cc++) {
        const int c = c0 + cc;
        float accA = bsa[c], accB = bs1[c];
#pragma unroll
        for (int q = 0; q < 16; q++) {
            float4 w = Wa4[c * 16 + q];
            float4 v = W14[c * 16 + q];
            accA += w.x*x[4*q] + w.y*x[4*q+1] + w.z*x[4*q+2] + w.w*x[4*q+3];
            accB += v.x*x[4*q] + v.y*x[4*q+1] + v.z*x[4*q+2] + v.w*x[4*q+3];
        }
        oA[cc] = accA; oB[cc] = accB;
    }
    float4* dstA = (float4*)(g_Ga + ((size_t)b * N_ + n) * 64 + c0);
    float4* dstB = (float4*)(g_G1 + ((size_t)b * N_ + n) * 64 + c0);
#pragma unroll
    for (int q = 0; q < 4; q++) {
        dstA[q] = make_float4(oA[4*q], oA[4*q+1], oA[4*q+2], oA[4*q+3]);
        dstB[q] = make_float4(oB[4*q], oB[4*q+1], oB[4*q+2], oB[4*q+3]);
    }
}

// ---------------------------------------------------------------------------
// smem layout (floats)
// ---------------------------------------------------------------------------
#define O_ATTN 0
#define O_HBUF 18432
#define O_REG  36864          // scratch (17408) then W2T/Wf1T/Wf2T (12288)
#define O_WAP  54272          // float4[64]
#define O_W1P  54528
#define O_BIAS 54784          // b2|bf1|bf2 (192)
#define O_FO   54976          // 512
#define O_G1   55488          // 512
#define O_DP0  56000
#define O_DP1  56256
#define O_DP2  56512
#define O_IDX  56768          // int[256]
#define SMEM_FLOATS 57024
#define SMEM_BYTES (SMEM_FLOATS * 4)

// ---------------------------------------------------------------------------
// main kernel: 8 points / block, 512 threads
// ---------------------------------------------------------------------------
__global__ void __launch_bounds__(512, 1) lpamlp_main_kernel(
    const float* __restrict__ p, const int* __restrict__ idx,
    const float* __restrict__ f,
    const float* __restrict__ Wa, const float* __restrict__ W1,
    const float* __restrict__ W2, const float* __restrict__ b2,
    const float* __restrict__ Wf1, const float* __restrict__ bf1,
    const float* __restrict__ Wf2, const float* __restrict__ bf2,
    float* __restrict__ out_f2)
{
    extern __shared__ float sm[];
    float*  attn   = sm + O_ATTN;
    float*  hbuf   = sm + O_HBUF;
    float*  scr    = sm + O_REG;            // scratch: 256 rows x 68
    float*  W2T    = sm + O_REG;            // later: [k][c]
    float*  Wf1T   = sm + O_REG + 4096;
    float*  Wf2T   = sm + O_REG + 8192;
    float4* Wap4   = (float4*)(sm + O_WAP);
    float4* W1p4   = (float4*)(sm + O_W1P);
    float*  bias   = sm + O_BIAS;
    float*  fo_sh  = sm + O_FO;
    float*  g1_sh  = sm + O_G1;
    float*  dp0    = sm + O_DP0;
    float*  dp1    = sm + O_DP1;
    float*  dp2    = sm + O_DP2;
    int*    idx_sh = (int*)(sm + O_IDX);

    const int tid = threadIdx.x;
    const int b = blockIdx.y, n0 = blockIdx.x * 8;
    const int w = tid >> 5, lane = tid & 31;

    // ---- pre: idx + dp per column; small weights ----
    if (tid < 256) {
        const int col = tid, pt = col >> 5, k = col & 31;
        const int n = n0 + pt;
        const int nb = idx[((size_t)b * N_ + n) * K_ + k];
        idx_sh[col] = nb;
        const float* pj = p + ((size_t)b * N_ + nb) * 3;
        const float* pc = p + ((size_t)b * N_ + n) * 3;
        dp0[col] = pj[0] - pc[0];
        dp1[col] = pj[1] - pc[1];
        dp2[col] = pj[2] - pc[2];
    }
    if (tid < 64) {
        Wap4[tid] = make_float4(Wa[tid*67], Wa[tid*67+1], Wa[tid*67+2], 0.f);
        W1p4[tid] = make_float4(W1[tid*67], W1[tid*67+1], W1[tid*67+2], 0.f);
        bias[tid]       = b2[tid];
        bias[64 + tid]  = bf1[tid];
        bias[128 + tid] = bf2[tid];
    }
    __syncthreads();

    const int g_nbr = lane >> 4, g_chk = lane & 15;

    // ---- gather Ga rows -> scratch (line-cooperative) ----
#pragma unroll
    for (int t = 0; t < 8; t++) {
        const int col = w * 16 + 2 * t + g_nbr;
        const int nb = idx_sh[col];
        float4 v = *(const float4*)(g_Ga + ((size_t)b * N_ + nb) * 64 + g_chk * 4);
        *(float4*)(scr + col * 68 + g_chk * 4) = v;
    }
    __syncthreads();

    // ---- transform: attn[c][col] = Ga + wa.dp ----
    {
        const int col = tid & 255, sub = tid >> 8;
        const int pt = col >> 5, k = col & 31;
        const int coff = pt * PS + k;
        const float d0 = dp0[col], d1 = dp1[col], d2 = dp2[col];
#pragma unroll
        for (int c4 = 0; c4 < 8; c4++) {
            float4 g = *(const float4*)(scr + col * 68 + sub * 32 + c4 * 4);
            const float gv[4] = {g.x, g.y, g.z, g.w};
#pragma unroll
            for (int j = 0; j < 4; j++) {
                const int c = sub * 32 + c4 * 4 + j;
                const float4 wa = Wap4[c];
                attn[c * RS + coff] = gv[j] + wa.x*d0 + wa.y*d1 + wa.z*d2;
            }
        }
    }
    __syncthreads();

    // ---- gather G1 rows -> scratch ----
#pragma unroll
    for (int t = 0; t < 8; t++) {
        const int col = w * 16 + 2 * t + g_nbr;
        const int nb = idx_sh[col];
        float4 v = *(const float4*)(g_G1 + ((size_t)b * N_ + nb) * 64 + g_chk * 4);
        *(float4*)(scr + col * 68 + g_chk * 4) = v;
    }
    __syncthreads();

    // ---- transform: hbuf[c][col] = relu(G1 + w1.dp) ----
    {
        const int col = tid & 255, sub = tid >> 8;
        const int pt = col >> 5, k = col & 31;
        const int coff = pt * PS + k;
        const float d0 = dp0[col], d1 = dp1[col], d2 = dp2[col];
#pragma unroll
        for (int c4 = 0; c4 < 8; c4++) {
            float4 g = *(const float4*)(scr + col * 68 + sub * 32 + c4 * 4);
            const float gv[4] = {g.x, g.y, g.z, g.w};
#pragma unroll
            for (int j = 0; j < 4; j++) {
                const int c = sub * 32 + c4 * 4 + j;
                const float4 w1 = W1p4[c];
                hbuf[c * RS + coff] = fmaxf(gv[j] + w1.x*d0 + w1.y*d1 + w1.z*d2, 0.f);
            }
        }
    }
    __syncthreads();

    // ---- phase S (softmax in-place on attn) + weight loads (independent) ----
    {
        const int c = tid >> 3, pt2 = tid & 7;
        float4* row = (float4*)(attn + c * RS + pt2 * PS);
        float4 v[8];
#pragma unroll
        for (int q = 0; q < 8; q++) v[q] = row[q];
        float m = -1e30f;
#pragma unroll
        for (int q = 0; q < 8; q++)
            m = fmaxf(m, fmaxf(fmaxf(v[q].x, v[q].y), fmaxf(v[q].z, v[q].w)));
        float s = 0.f;
#pragma unroll
        for (int q = 0; q < 8; q++) {
            v[q].x = __expf(v[q].x - m); v[q].y = __expf(v[q].y - m);
            v[q].z = __expf(v[q].z - m); v[q].w = __expf(v[q].w - m);
            s += (v[q].x + v[q].y) + (v[q].z + v[q].w);
        }
        const float inv = __fdividef(1.f, s);
#pragma unroll
        for (int q = 0; q < 8; q++) {
            v[q].x *= inv; v[q].y *= inv; v[q].z *= inv; v[q].w *= inv;
            row[q] = v[q];
        }
    }
    // overwrite scratch with W2T/Wf1T/Wf2T (scratch no longer needed)
    for (int i = tid; i < 4096; i += 512) {
        const int r = i >> 6, c = i & 63;
        W2T[c * 64 + r] = W2[i];      // [k][c]
        Wf1T[c * 64 + r] = Wf1[i];    // [i][o]
        Wf2T[c * 64 + r] = Wf2[i];
    }
    __syncthreads();

    // ---- phase M: fo = sum_k ca .* (W2 @ h), f32x2-packed ----
    {
        const int chan0 = (w & 7) * 8;
        const int half = w >> 3;
        const int ptl = lane >> 3, q = lane & 7;
        const int pt = half * 4 + ptl;
        const int colbase = pt * PS + q * 4;

        u64 acc2[4][4];
#pragma unroll
        for (int a = 0; a < 4; a++)
#pragma unroll
            for (int j = 0; j < 4; j++) acc2[a][j] = 0ull;

#pragma unroll 4
        for (int k = 0; k < 64; k++) {
            const ulonglong2 a01 = *(const ulonglong2*)(W2T + k * 64 + chan0);
            const ulonglong2 a23 = *(const ulonglong2*)(W2T + k * 64 + chan0 + 4);
            const float4 bv = *(const float4*)(hbuf + k * RS + colbase);
            const u64 bb0 = pk2(bv.x, bv.x), bb1 = pk2(bv.y, bv.y);
            const u64 bb2 = pk2(bv.z, bv.z), bb3 = pk2(bv.w, bv.w);
            fma2(acc2[0][0], a01.x, bb0); fma2(acc2[0][1], a01.x, bb1);
            fma2(acc2[0][2], a01.x, bb2); fma2(acc2[0][3], a01.x, bb3);
            fma2(acc2[1][0], a01.y, bb0); fma2(acc2[1][1], a01.y, bb1);
            fma2(acc2[1][2], a01.y, bb2); fma2(acc2[1][3], a01.y, bb3);
            fma2(acc2[2][0], a23.x, bb0); fma2(acc2[2][1], a23.x, bb1);
            fma2(acc2[2][2], a23.x, bb2); fma2(acc2[2][3], a23.x, bb3);
            fma2(acc2[3][0], a23.y, bb0); fma2(acc2[3][1], a23.y, bb1);
            fma2(acc2[3][2], a23.y, bb2); fma2(acc2[3][3], a23.y, bb3);
        }

#pragma unroll
        for (int a = 0; a < 4; a++) {
            const int ce = chan0 + 2 * a, co = ce + 1;
            const float4 ue = *(const float4*)(attn + ce * RS + colbase);
            const float4 uo = *(const float4*)(attn + co * RS + colbase);
            u64 part = 0ull;
            fma2(part, pk2(ue.x, uo.x), acc2[a][0]);
            fma2(part, pk2(ue.y, uo.y), acc2[a][1]);
            fma2(part, pk2(ue.z, uo.z), acc2[a][2]);
            fma2(part, pk2(ue.w, uo.w), acc2[a][3]);
#pragma unroll
            for (int o = 1; o < 8; o <<= 1)
                part = add2(part, (u64)__shfl_xor_sync(0xffffffffu,
                                    (unsigned long long)part, o));
            if (q == 0) {
                float pe, po;
                upk2(pe, po, part);
                const float fre = f[((size_t)b * 64 + ce) * N_ + n0 + pt];
                const float fro = f[((size_t)b * 64 + co) * N_ + n0 + pt];
                fo_sh[pt * 64 + ce] = fmaxf(pe + bias[ce] + fre, 0.f);
                fo_sh[pt * 64 + co] = fmaxf(po + bias[co] + fro, 0.f);
            }
        }
    }
    __syncthreads();

    // ---- phase F: FFN, 1 output channel per thread (2 warps per point) ----
    {
        const int fpt = w >> 1;
        const int c = (w & 1) * 32 + lane;
        float g1 = bias[64 + c];
#pragma unroll
        for (int i = 0; i < 64; i++)
            g1 += fo_sh[fpt * 64 + i] * Wf1T[i * 64 + c];
        g1_sh[fpt * 64 + c] = fmaxf(g1, 0.f);
        __syncthreads();

        float g2 = bias[128 + c];
#pragma unroll
        for (int i = 0; i < 64; i++)
            g2 += g1_sh[fpt * 64 + i] * Wf2T[i * 64 + c];
        out_f2[((size_t)b * 64 + c) * N_ + n0 + fpt] =
            fmaxf(g2 + fo_sh[fpt * 64 + c], 0.f);
    }
}

// ---------------------------------------------------------------------------
// launch
// ---------------------------------------------------------------------------
extern "C" void kernel_launch(void* const* d_in, const int* in_sizes, int n_in,
                              void* d_out, int out_size)
{
    const float* p      = (const float*)d_in[0];
    const float* f      = (const float*)d_in[1];
    const int*   idx    = (const int*)d_in[2];
    const float* W_attn = (const float*)d_in[3];
    const float* b_attn = (const float*)d_in[4];
    const float* W1     = (const float*)d_in[5];
    const float* b1     = (const float*)d_in[6];
    const float* W2     = (const float*)d_in[7];
    const float* b2     = (const float*)d_in[8];
    const float* Wf1    = (const float*)d_in[9];
    const float* bf1    = (const float*)d_in[10];
    const float* Wf2    = (const float*)d_in[11];
    const float* bf2    = (const float*)d_in[12];

    float* out = (float*)d_out;
    const int psz = B_ * N_ * 3;
    const int fsz = B_ * C_ * N_;

    float* out_f2 = out;
    if (out_size >= psz + fsz) {
        cudaMemcpyAsync(out, p, (size_t)psz * sizeof(float),
                        cudaMemcpyDeviceToDevice);
        out_f2 = out + psz;
    }

    precompute_kernel<<<dim3(N_ / 64, B_), 256>>>(f, W_attn, b_attn, W1, b1);

    cudaFuncSetAttribute(lpamlp_main_kernel,
                         cudaFuncAttributeMaxDynamicSharedMemorySize, SMEM_BYTES);
    lpamlp_main_kernel<<<dim3(N_ / 8, B_), 512, SMEM_BYTES>>>(
        p, idx, f, W_attn, W1, W2, b2, Wf1, bf1, Wf2, bf2, out_f2);
}

// round 7
// speedup vs baseline: 1.5043x; 1.2451x over previous
#include <cuda_runtime.h>
#include <cstdint>
#include <cstddef>

#define B_ 4
#define N_ 8192
#define K_ 32
#define C_ 64

#define RS 288   // attn/h row stride in floats (8 pts * 36)
#define PS 36    // per-point column-slot stride in floats
#define WS 68    // padded stride for transposed weights / fo / g1

typedef unsigned long long u64;

__device__ __forceinline__ void fma2(u64& d, u64 a, u64 b) {
    asm("fma.rn.f32x2 %0, %1, %2, %0;" : "+l"(d) : "l"(a), "l"(b));
}
__device__ __forceinline__ u64 add2(u64 a, u64 b) {
    u64 r; asm("add.rn.f32x2 %0, %1, %2;" : "=l"(r) : "l"(a), "l"(b)); return r;
}
__device__ __forceinline__ u64 pk2(float lo, float hi) {
    u64 r; asm("mov.b64 %0, {%1, %2};" : "=l"(r) : "f"(lo), "f"(hi)); return r;
}
__device__ __forceinline__ void upk2(float& lo, float& hi, u64 v) {
    asm("mov.b64 {%0, %1}, %2;" : "=f"(lo), "=f"(hi) : "l"(v));
}

// precomputed linear parts: Ga = Wa_f @ f + b_attn, G1 = W1_f @ f + b1
__device__ float g_Ga[(size_t)B_ * N_ * C_];
__device__ float g_G1[(size_t)B_ * N_ * C_];

// ---------------------------------------------------------------------------
// precompute kernel: 64 points per block, 256 threads
// ---------------------------------------------------------------------------
__global__ void __launch_bounds__(256) precompute_kernel(
    const float* __restrict__ f,
    const float* __restrict__ Wa, const float* __restrict__ ba,
    const float* __restrict__ W1, const float* __restrict__ b1)
{
    __shared__ float4 Wa4[1024];
    __shared__ float4 W14[1024];
    __shared__ float bsa[64], bs1[64];
    const int tid = threadIdx.x;
    const int b = blockIdx.y, n0 = blockIdx.x * 64;

    for (int i = tid; i < 1024; i += 256) {
        int c = i >> 4, j = (i & 15) * 4;
        Wa4[i] = make_float4(Wa[c*67+3+j], Wa[c*67+4+j], Wa[c*67+5+j], Wa[c*67+6+j]);
        W14[i] = make_float4(W1[c*67+3+j], W1[c*67+4+j], W1[c*67+5+j], W1[c*67+6+j]);
    }
    if (tid < 64) { bsa[tid] = ba[tid]; bs1[tid] = b1[tid]; }
    __syncthreads();

    const int nl = tid & 63, c0 = (tid >> 6) * 16;
    const int n = n0 + nl;
    float x[64];
#pragma unroll
    for (int i = 0; i < 64; i++) x[i] = f[((size_t)b * 64 + i) * N_ + n];

    float oA[16], oB[16];
#pragma unroll
    for (int cc = 0; cc < 16; cc++) {
        const int c = c0 + cc;
        float accA = bsa[c], accB = bs1[c];
#pragma unroll
        for (int q = 0; q < 16; q++) {
            float4 w = Wa4[c * 16 + q];
            float4 v = W14[c * 16 + q];
            accA += w.x*x[4*q] + w.y*x[4*q+1] + w.z*x[4*q+2] + w.w*x[4*q+3];
            accB += v.x*x[4*q] + v.y*x[4*q+1] + v.z*x[4*q+2] + v.w*x[4*q+3];
        }
        oA[cc] = accA; oB[cc] = accB;
    }
    float4* dstA = (float4*)(g_Ga + ((size_t)b * N_ + n) * 64 + c0);
    float4* dstB = (float4*)(g_G1 + ((size_t)b * N_ + n) * 64 + c0);
#pragma unroll
    for (int q = 0; q < 4; q++) {
        dstA[q] = make_float4(oA[4*q], oA[4*q+1], oA[4*q+2], oA[4*q+3]);
        dstB[q] = make_float4(oB[4*q], oB[4*q+1], oB[4*q+2], oB[4*q+3]);
    }
}

// ---------------------------------------------------------------------------
// smem layout (floats)
// ---------------------------------------------------------------------------
#define O_ATTN 0
#define O_HBUF 18432
#define O_REG  36864          // scratch 256x68 (17408) then padded W2T/Wf1T/Wf2T
#define O_WAP  54272          // float4[64]
#define O_W1P  54528
#define O_BIAS 54784          // b2|bf1|bf2 (192)
#define O_FO   54976          // 8*68 = 544
#define O_G1   55520          // 544
#define O_DP0  56064
#define O_DP1  56320
#define O_DP2  56576
#define O_IDX  56832          // int[256]
#define SMEM_FLOATS 57088
#define SMEM_BYTES (SMEM_FLOATS * 4)

// ---------------------------------------------------------------------------
// main kernel: 8 points / block, 512 threads
// ---------------------------------------------------------------------------
__global__ void __launch_bounds__(512, 1) lpamlp_main_kernel(
    const float* __restrict__ p, const int* __restrict__ idx,
    const float* __restrict__ f,
    const float* __restrict__ Wa, const float* __restrict__ W1,
    const float* __restrict__ W2, const float* __restrict__ b2,
    const float* __restrict__ Wf1, const float* __restrict__ bf1,
    const float* __restrict__ Wf2, const float* __restrict__ bf2,
    float* __restrict__ out_f2)
{
    extern __shared__ float sm[];
    float*  attn   = sm + O_ATTN;
    float*  hbuf   = sm + O_HBUF;
    float*  scr    = sm + O_REG;             // scratch: 256 rows x 68
    float*  W2T    = sm + O_REG;             // later: [k][c] stride 68
    float*  Wf1T   = sm + O_REG + 4352;      // [i][o] stride 68
    float*  Wf2T   = sm + O_REG + 8704;
    float4* Wap4   = (float4*)(sm + O_WAP);
    float4* W1p4   = (float4*)(sm + O_W1P);
    float*  bias   = sm + O_BIAS;
    float*  fo_sh  = sm + O_FO;              // [pt][c] stride 68
    float*  g1_sh  = sm + O_G1;
    float*  dp0    = sm + O_DP0;
    float*  dp1    = sm + O_DP1;
    float*  dp2    = sm + O_DP2;
    int*    idx_sh = (int*)(sm + O_IDX);

    const int tid = threadIdx.x;
    const int b = blockIdx.y, n0 = blockIdx.x * 8;
    const int w = tid >> 5, lane = tid & 31;

    // ---- pre: idx + dp per column; small weights ----
    if (tid < 256) {
        const int col = tid, pt = col >> 5, k = col & 31;
        const int n = n0 + pt;
        const int nb = idx[((size_t)b * N_ + n) * K_ + k];
        idx_sh[col] = nb;
        const float* pj = p + ((size_t)b * N_ + nb) * 3;
        const float* pc = p + ((size_t)b * N_ + n) * 3;
        dp0[col] = pj[0] - pc[0];
        dp1[col] = pj[1] - pc[1];
        dp2[col] = pj[2] - pc[2];
    }
    if (tid < 64) {
        Wap4[tid] = make_float4(Wa[tid*67], Wa[tid*67+1], Wa[tid*67+2], 0.f);
        W1p4[tid] = make_float4(W1[tid*67], W1[tid*67+1], W1[tid*67+2], 0.f);
        bias[tid]       = b2[tid];
        bias[64 + tid]  = bf1[tid];
        bias[128 + tid] = bf2[tid];
    }
    __syncthreads();

    const int g_nbr = lane >> 4, g_chk = lane & 15;

    // ---- gather Ga rows -> scratch (line-cooperative) ----
#pragma unroll
    for (int t = 0; t < 8; t++) {
        const int col = w * 16 + 2 * t + g_nbr;
        const int nb = idx_sh[col];
        float4 v = *(const float4*)(g_Ga + ((size_t)b * N_ + nb) * 64 + g_chk * 4);
        *(float4*)(scr + col * 68 + g_chk * 4) = v;
    }
    __syncthreads();

    // ---- transform: attn[c][col] = Ga + wa.dp ----
    {
        const int col = tid & 255, sub = tid >> 8;
        const int pt = col >> 5, k = col & 31;
        const int coff = pt * PS + k;
        const float d0 = dp0[col], d1 = dp1[col], d2 = dp2[col];
#pragma unroll
        for (int c4 = 0; c4 < 8; c4++) {
            float4 g = *(const float4*)(scr + col * 68 + sub * 32 + c4 * 4);
            const float gv[4] = {g.x, g.y, g.z, g.w};
#pragma unroll
            for (int j = 0; j < 4; j++) {
                const int c = sub * 32 + c4 * 4 + j;
                const float4 wa = Wap4[c];
                attn[c * RS + coff] = gv[j] + wa.x*d0 + wa.y*d1 + wa.z*d2;
            }
        }
    }
    __syncthreads();

    // ---- gather G1 rows -> scratch ----
#pragma unroll
    for (int t = 0; t < 8; t++) {
        const int col = w * 16 + 2 * t + g_nbr;
        const int nb = idx_sh[col];
        float4 v = *(const float4*)(g_G1 + ((size_t)b * N_ + nb) * 64 + g_chk * 4);
        *(float4*)(scr + col * 68 + g_chk * 4) = v;
    }
    __syncthreads();

    // ---- transform: hbuf[c][col] = relu(G1 + w1.dp) ----
    {
        const int col = tid & 255, sub = tid >> 8;
        const int pt = col >> 5, k = col & 31;
        const int coff = pt * PS + k;
        const float d0 = dp0[col], d1 = dp1[col], d2 = dp2[col];
#pragma unroll
        for (int c4 = 0; c4 < 8; c4++) {
            float4 g = *(const float4*)(scr + col * 68 + sub * 32 + c4 * 4);
            const float gv[4] = {g.x, g.y, g.z, g.w};
#pragma unroll
            for (int j = 0; j < 4; j++) {
                const int c = sub * 32 + c4 * 4 + j;
                const float4 w1 = W1p4[c];
                hbuf[c * RS + coff] = fmaxf(gv[j] + w1.x*d0 + w1.y*d1 + w1.z*d2, 0.f);
            }
        }
    }
    __syncthreads();

    // ---- phase S (softmax in-place on attn) + padded weight staging ----
    {
        const int c = tid >> 3, pt2 = tid & 7;
        float4* row = (float4*)(attn + c * RS + pt2 * PS);
        float4 v[8];
#pragma unroll
        for (int q = 0; q < 8; q++) v[q] = row[q];
        float m = -1e30f;
#pragma unroll
        for (int q = 0; q < 8; q++)
            m = fmaxf(m, fmaxf(fmaxf(v[q].x, v[q].y), fmaxf(v[q].z, v[q].w)));
        float s = 0.f;
#pragma unroll
        for (int q = 0; q < 8; q++) {
            v[q].x = __expf(v[q].x - m); v[q].y = __expf(v[q].y - m);
            v[q].z = __expf(v[q].z - m); v[q].w = __expf(v[q].w - m);
            s += (v[q].x + v[q].y) + (v[q].z + v[q].w);
        }
        const float inv = __fdividef(1.f, s);
#pragma unroll
        for (int q = 0; q < 8; q++) {
            v[q].x *= inv; v[q].y *= inv; v[q].z *= inv; v[q].w *= inv;
            row[q] = v[q];
        }
    }
    // stage weights into padded-transposed layout (4-way max conflicts)
    for (int i = tid; i < 4096; i += 512) {
        const int r = i >> 6, c = i & 63;       // source [r][c], lanes vary c
        W2T[c * WS + r]  = W2[i];               // W2T[k][o] = W2[o][k]
        Wf1T[c * WS + r] = Wf1[i];              // Wf1T[in][o]
        Wf2T[c * WS + r] = Wf2[i];
    }
    __syncthreads();

    // ---- phase M: fo = sum_k ca .* (W2 @ h), f32x2-packed ----
    {
        const int chan0 = (w & 7) * 8;
        const int half = w >> 3;
        const int ptl = lane >> 3, q = lane & 7;
        const int pt = half * 4 + ptl;
        const int colbase = pt * PS + q * 4;

        u64 acc2[4][4];
#pragma unroll
        for (int a = 0; a < 4; a++)
#pragma unroll
            for (int j = 0; j < 4; j++) acc2[a][j] = 0ull;

#pragma unroll 4
        for (int k = 0; k < 64; k++) {
            const ulonglong2 a01 = *(const ulonglong2*)(W2T + k * WS + chan0);
            const ulonglong2 a23 = *(const ulonglong2*)(W2T + k * WS + chan0 + 4);
            const float4 bv = *(const float4*)(hbuf + k * RS + colbase);
            const u64 bb0 = pk2(bv.x, bv.x), bb1 = pk2(bv.y, bv.y);
            const u64 bb2 = pk2(bv.z, bv.z), bb3 = pk2(bv.w, bv.w);
            fma2(acc2[0][0], a01.x, bb0); fma2(acc2[0][1], a01.x, bb1);
            fma2(acc2[0][2], a01.x, bb2); fma2(acc2[0][3], a01.x, bb3);
            fma2(acc2[1][0], a01.y, bb0); fma2(acc2[1][1], a01.y, bb1);
            fma2(acc2[1][2], a01.y, bb2); fma2(acc2[1][3], a01.y, bb3);
            fma2(acc2[2][0], a23.x, bb0); fma2(acc2[2][1], a23.x, bb1);
            fma2(acc2[2][2], a23.x, bb2); fma2(acc2[2][3], a23.x, bb3);
            fma2(acc2[3][0], a23.y, bb0); fma2(acc2[3][1], a23.y, bb1);
            fma2(acc2[3][2], a23.y, bb2); fma2(acc2[3][3], a23.y, bb3);
        }

#pragma unroll
        for (int a = 0; a < 4; a++) {
            const int ce = chan0 + 2 * a, co = ce + 1;
            const float4 ue = *(const float4*)(attn + ce * RS + colbase);
            const float4 uo = *(const float4*)(attn + co * RS + colbase);
            u64 part = 0ull;
            fma2(part, pk2(ue.x, uo.x), acc2[a][0]);
            fma2(part, pk2(ue.y, uo.y), acc2[a][1]);
            fma2(part, pk2(ue.z, uo.z), acc2[a][2]);
            fma2(part, pk2(ue.w, uo.w), acc2[a][3]);
#pragma unroll
            for (int o = 1; o < 8; o <<= 1)
                part = add2(part, (u64)__shfl_xor_sync(0xffffffffu,
                                    (unsigned long long)part, o));
            if (q == 0) {
                float pe, po;
                upk2(pe, po, part);
                const float fre = f[((size_t)b * 64 + ce) * N_ + n0 + pt];
                const float fro = f[((size_t)b * 64 + co) * N_ + n0 + pt];
                fo_sh[pt * WS + ce] = fmaxf(pe + bias[ce] + fre, 0.f);
                fo_sh[pt * WS + co] = fmaxf(po + bias[co] + fro, 0.f);
            }
        }
    }
    __syncthreads();

    // ---- phase F: FFN, thread = (c = w*4 + lane>>3, pt = lane&7) ----
    {
        const int c = w * 4 + (lane >> 3);
        const int fpt = lane & 7;
        float g1 = bias[64 + c];
#pragma unroll
        for (int i = 0; i < 64; i++)
            g1 += fo_sh[fpt * WS + i] * Wf1T[i * WS + c];
        g1_sh[fpt * WS + c] = fmaxf(g1, 0.f);
        __syncthreads();

        float g2 = bias[128 + c];
#pragma unroll
        for (int i = 0; i < 64; i++)
            g2 += g1_sh[fpt * WS + i] * Wf2T[i * WS + c];
        out_f2[((size_t)b * 64 + c) * N_ + n0 + fpt] =
            fmaxf(g2 + fo_sh[fpt * WS + c], 0.f);
    }
}

// ---------------------------------------------------------------------------
// launch
// ---------------------------------------------------------------------------
extern "C" void kernel_launch(void* const* d_in, const int* in_sizes, int n_in,
                              void* d_out, int out_size)
{
    const float* p      = (const float*)d_in[0];
    const float* f      = (const float*)d_in[1];
    const int*   idx    = (const int*)d_in[2];
    const float* W_attn = (const float*)d_in[3];
    const float* b_attn = (const float*)d_in[4];
    const float* W1     = (const float*)d_in[5];
    const float* b1     = (const float*)d_in[6];
    const float* W2     = (const float*)d_in[7];
    const float* b2     = (const float*)d_in[8];
    const float* Wf1    = (const float*)d_in[9];
    const float* bf1    = (const float*)d_in[10];
    const float* Wf2    = (const float*)d_in[11];
    const float* bf2    = (const float*)d_in[12];

    float* out = (float*)d_out;
    const int psz = B_ * N_ * 3;
    const int fsz = B_ * C_ * N_;

    float* out_f2 = out;
    if (out_size >= psz + fsz) {
        cudaMemcpyAsync(out, p, (size_t)psz * sizeof(float),
                        cudaMemcpyDeviceToDevice);
        out_f2 = out + psz;
    }

    precompute_kernel<<<dim3(N_ / 64, B_), 256>>>(f, W_attn, b_attn, W1, b1);

    cudaFuncSetAttribute(lpamlp_main_kernel,
                         cudaFuncAttributeMaxDynamicSharedMemorySize, SMEM_BYTES);
    lpamlp_main_kernel<<<dim3(N_ / 8, B_), 512, SMEM_BYTES>>>(
        p, idx, f, W_attn, W1, W2, b2, Wf1, bf1, Wf2, bf2, out_f2);
}

// round 8
// speedup vs baseline: 1.5325x; 1.0187x over previous
#include <cuda_runtime.h>
#include <cstdint>
#include <cstddef>

#define B_ 4
#define N_ 8192
#define K_ 32
#define C_ 64

#define RS 288   // attn/h row stride in floats (8 pts * 36)
#define PS 36    // per-point column-slot stride in floats
#define WS 68    // padded stride for weights / fo / g1

typedef unsigned long long u64;

__device__ __forceinline__ void fma2(u64& d, u64 a, u64 b) {
    asm("fma.rn.f32x2 %0, %1, %2, %0;" : "+l"(d) : "l"(a), "l"(b));
}
__device__ __forceinline__ u64 add2(u64 a, u64 b) {
    u64 r; asm("add.rn.f32x2 %0, %1, %2;" : "=l"(r) : "l"(a), "l"(b)); return r;
}
__device__ __forceinline__ u64 pk2(float lo, float hi) {
    u64 r; asm("mov.b64 %0, {%1, %2};" : "=l"(r) : "f"(lo), "f"(hi)); return r;
}
__device__ __forceinline__ void upk2(float& lo, float& hi, u64 v) {
    asm("mov.b64 {%0, %1}, %2;" : "=f"(lo), "=f"(hi) : "l"(v));
}

// precomputed linear parts: Ga = Wa_f @ f + b_attn, G1 = W1_f @ f + b1
__device__ float g_Ga[(size_t)B_ * N_ * C_];
__device__ float g_G1[(size_t)B_ * N_ * C_];

// ---------------------------------------------------------------------------
// precompute kernel: 64 points per block, 256 threads
// ---------------------------------------------------------------------------
__global__ void __launch_bounds__(256) precompute_kernel(
    const float* __restrict__ f,
    const float* __restrict__ Wa, const float* __restrict__ ba,
    const float* __restrict__ W1, const float* __restrict__ b1)
{
    __shared__ float4 Wa4[1024];
    __shared__ float4 W14[1024];
    __shared__ float bsa[64], bs1[64];
    const int tid = threadIdx.x;
    const int b = blockIdx.y, n0 = blockIdx.x * 64;

    for (int i = tid; i < 1024; i += 256) {
        int c = i >> 4, j = (i & 15) * 4;
        Wa4[i] = make_float4(Wa[c*67+3+j], Wa[c*67+4+j], Wa[c*67+5+j], Wa[c*67+6+j]);
        W14[i] = make_float4(W1[c*67+3+j], W1[c*67+4+j], W1[c*67+5+j], W1[c*67+6+j]);
    }
    if (tid < 64) { bsa[tid] = ba[tid]; bs1[tid] = b1[tid]; }
    __syncthreads();

    const int nl = tid & 63, c0 = (tid >> 6) * 16;
    const int n = n0 + nl;
    float x[64];
#pragma unroll
    for (int i = 0; i < 64; i++) x[i] = f[((size_t)b * 64 + i) * N_ + n];

    float oA[16], oB[16];
#pragma unroll
    for (int cc = 0; cc < 16; cc++) {
        const int c = c0 + cc;
        float accA = bsa[c], accB = bs1[c];
#pragma unroll
        for (int q = 0; q < 16; q++) {
            float4 w = Wa4[c * 16 + q];
            float4 v = W14[c * 16 + q];
            accA += w.x*x[4*q] + w.y*x[4*q+1] + w.z*x[4*q+2] + w.w*x[4*q+3];
            accB += v.x*x[4*q] + v.y*x[4*q+1] + v.z*x[4*q+2] + v.w*x[4*q+3];
        }
        oA[cc] = accA; oB[cc] = accB;
    }
    float4* dstA = (float4*)(g_Ga + ((size_t)b * N_ + n) * 64 + c0);
    float4* dstB = (float4*)(g_G1 + ((size_t)b * N_ + n) * 64 + c0);
#pragma unroll
    for (int q = 0; q < 4; q++) {
        dstA[q] = make_float4(oA[4*q], oA[4*q+1], oA[4*q+2], oA[4*q+3]);
        dstB[q] = make_float4(oB[4*q], oB[4*q+1], oB[4*q+2], oB[4*q+3]);
    }
}

// ---------------------------------------------------------------------------
// smem layout (floats)
// ---------------------------------------------------------------------------
#define O_ATTN 0
#define O_HBUF 18432
#define O_REG  36864          // scratch 256x68 (17408); then W2T|Wf1R|Wf2R
#define O_WAP  54272          // float4[64]
#define O_W1P  54528
#define O_BIAS 54784          // b2|bf1|bf2 (192)
#define O_FP0  54976          // fo partial khalf=0, later fo (8*68)
#define O_FP1  55520          // fo partial khalf=1
#define O_G1   56064          // 544
#define O_DP0  56608
#define O_DP1  56864
#define O_DP2  57120
#define O_IDX  57376          // int[256]
#define SMEM_FLOATS 57632
#define SMEM_BYTES (SMEM_FLOATS * 4)

// ---------------------------------------------------------------------------
// main kernel: 8 points / block, 512 threads
// ---------------------------------------------------------------------------
__global__ void __launch_bounds__(512, 1) lpamlp_main_kernel(
    const float* __restrict__ p, const int* __restrict__ idx,
    const float* __restrict__ f,
    const float* __restrict__ Wa, const float* __restrict__ W1,
    const float* __restrict__ W2, const float* __restrict__ b2,
    const float* __restrict__ Wf1, const float* __restrict__ bf1,
    const float* __restrict__ Wf2, const float* __restrict__ bf2,
    float* __restrict__ out_f2)
{
    extern __shared__ float sm[];
    float*  attn   = sm + O_ATTN;
    float*  hbuf   = sm + O_HBUF;
    float*  scr    = sm + O_REG;             // scratch: 256 rows x 68
    float*  W2T    = sm + O_REG;             // later: [k][o] stride 68
    float*  Wf1R   = sm + O_REG + 4352;      // [o][i] stride 68
    float*  Wf2R   = sm + O_REG + 8704;      // [o][i] stride 68
    float4* Wap4   = (float4*)(sm + O_WAP);
    float4* W1p4   = (float4*)(sm + O_W1P);
    float*  bias   = sm + O_BIAS;
    float*  fp0    = sm + O_FP0;             // [pt][c] stride 68
    float*  fp1    = sm + O_FP1;
    float*  g1_sh  = sm + O_G1;
    float*  dp0    = sm + O_DP0;
    float*  dp1    = sm + O_DP1;
    float*  dp2    = sm + O_DP2;
    int*    idx_sh = (int*)(sm + O_IDX);

    const int tid = threadIdx.x;
    const int b = blockIdx.y, n0 = blockIdx.x * 8;
    const int w = tid >> 5, lane = tid & 31;

    // ---- pre: idx + dp per column; small weights ----
    if (tid < 256) {
        const int col = tid, pt = col >> 5, k = col & 31;
        const int n = n0 + pt;
        const int nb = idx[((size_t)b * N_ + n) * K_ + k];
        idx_sh[col] = nb;
        const float* pj = p + ((size_t)b * N_ + nb) * 3;
        const float* pc = p + ((size_t)b * N_ + n) * 3;
        dp0[col] = pj[0] - pc[0];
        dp1[col] = pj[1] - pc[1];
        dp2[col] = pj[2] - pc[2];
    }
    if (tid < 64) {
        Wap4[tid] = make_float4(Wa[tid*67], Wa[tid*67+1], Wa[tid*67+2], 0.f);
        W1p4[tid] = make_float4(W1[tid*67], W1[tid*67+1], W1[tid*67+2], 0.f);
        bias[tid]       = b2[tid];
        bias[64 + tid]  = bf1[tid];
        bias[128 + tid] = bf2[tid];
    }
    __syncthreads();

    const int g_nbr = lane >> 4, g_chk = lane & 15;

    // ---- gather Ga rows -> scratch (line-cooperative) ----
#pragma unroll
    for (int t = 0; t < 8; t++) {
        const int col = w * 16 + 2 * t + g_nbr;
        const int nb = idx_sh[col];
        float4 v = *(const float4*)(g_Ga + ((size_t)b * N_ + nb) * 64 + g_chk * 4);
        *(float4*)(scr + col * 68 + g_chk * 4) = v;
    }
    __syncthreads();

    // ---- transform: attn[c][col] = Ga + wa.dp ----
    {
        const int col = tid & 255, sub = tid >> 8;
        const int pt = col >> 5, k = col & 31;
        const int coff = pt * PS + k;
        const float d0 = dp0[col], d1 = dp1[col], d2 = dp2[col];
#pragma unroll
        for (int c4 = 0; c4 < 8; c4++) {
            float4 g = *(const float4*)(scr + col * 68 + sub * 32 + c4 * 4);
            const float gv[4] = {g.x, g.y, g.z, g.w};
#pragma unroll
            for (int j = 0; j < 4; j++) {
                const int c = sub * 32 + c4 * 4 + j;
                const float4 wa = Wap4[c];
                attn[c * RS + coff] = gv[j] + wa.x*d0 + wa.y*d1 + wa.z*d2;
            }
        }
    }
    __syncthreads();

    // ---- gather G1 rows -> scratch ----
#pragma unroll
    for (int t = 0; t < 8; t++) {
        const int col = w * 16 + 2 * t + g_nbr;
        const int nb = idx_sh[col];
        float4 v = *(const float4*)(g_G1 + ((size_t)b * N_ + nb) * 64 + g_chk * 4);
        *(float4*)(scr + col * 68 + g_chk * 4) = v;
    }
    __syncthreads();

    // ---- transform: hbuf[c][col] = relu(G1 + w1.dp) ----
    {
        const int col = tid & 255, sub = tid >> 8;
        const int pt = col >> 5, k = col & 31;
        const int coff = pt * PS + k;
        const float d0 = dp0[col], d1 = dp1[col], d2 = dp2[col];
#pragma unroll
        for (int c4 = 0; c4 < 8; c4++) {
            float4 g = *(const float4*)(scr + col * 68 + sub * 32 + c4 * 4);
            const float gv[4] = {g.x, g.y, g.z, g.w};
#pragma unroll
            for (int j = 0; j < 4; j++) {
                const int c = sub * 32 + c4 * 4 + j;
                const float4 w1 = W1p4[c];
                hbuf[c * RS + coff] = fmaxf(gv[j] + w1.x*d0 + w1.y*d1 + w1.z*d2, 0.f);
            }
        }
    }
    __syncthreads();

    // ---- phase S (softmax in-place on attn) + weight staging ----
    {
        const int c = tid >> 3, pt2 = tid & 7;
        float4* row = (float4*)(attn + c * RS + pt2 * PS);
        float4 v[8];
#pragma unroll
        for (int q = 0; q < 8; q++) v[q] = row[q];
        float m = -1e30f;
#pragma unroll
        for (int q = 0; q < 8; q++)
            m = fmaxf(m, fmaxf(fmaxf(v[q].x, v[q].y), fmaxf(v[q].z, v[q].w)));
        float s = 0.f;
#pragma unroll
        for (int q = 0; q < 8; q++) {
            v[q].x = __expf(v[q].x - m); v[q].y = __expf(v[q].y - m);
            v[q].z = __expf(v[q].z - m); v[q].w = __expf(v[q].w - m);
            s += (v[q].x + v[q].y) + (v[q].z + v[q].w);
        }
        const float inv = __fdividef(1.f, s);
#pragma unroll
        for (int q = 0; q < 8; q++) {
            v[q].x *= inv; v[q].y *= inv; v[q].z *= inv; v[q].w *= inv;
            row[q] = v[q];
        }
    }
    // stage weights (scratch no longer needed)
    for (int i = tid; i < 4096; i += 512) {
        const int r = i >> 6, cc = i & 63;      // lanes vary cc
        W2T[cc * WS + r]  = W2[i];              // [k_in][o], 4-way stores
        Wf1R[r * WS + cc] = Wf1[i];             // [o][i], conflict-free
        Wf2R[r * WS + cc] = Wf2[i];
    }
    __syncthreads();

    // ---- phase M: partial fo = sum_k(ca .* W2@h), 16ch x 128col x 32k / warp
    {
        const int chan0 = (w >> 2) * 16;
        const int half  = (w >> 1) & 1;
        const int khalf = w & 1;
        float* fop = khalf ? fp1 : fp0;
        const int ptl = lane >> 3, q = lane & 7;
        const int pt = half * 4 + ptl;
        const int colbase = pt * PS + q * 4;

        u64 acc2[8][4];
#pragma unroll
        for (int a = 0; a < 8; a++)
#pragma unroll
            for (int j = 0; j < 4; j++) acc2[a][j] = 0ull;

        const float* hrow = hbuf + khalf * 32 * RS;
        const float* wrow = W2T + khalf * 32 * WS + chan0;
#pragma unroll 4
        for (int kk = 0; kk < 32; kk++) {
            const ulonglong2 aA = *(const ulonglong2*)(wrow + kk * WS);
            const ulonglong2 aB = *(const ulonglong2*)(wrow + kk * WS + 4);
            const ulonglong2 aC = *(const ulonglong2*)(wrow + kk * WS + 8);
            const ulonglong2 aD = *(const ulonglong2*)(wrow + kk * WS + 12);
            const float4 bv = *(const float4*)(hrow + kk * RS + colbase);
            const u64 bb0 = pk2(bv.x, bv.x), bb1 = pk2(bv.y, bv.y);
            const u64 bb2 = pk2(bv.z, bv.z), bb3 = pk2(bv.w, bv.w);
            fma2(acc2[0][0], aA.x, bb0); fma2(acc2[0][1], aA.x, bb1);
            fma2(acc2[0][2], aA.x, bb2); fma2(acc2[0][3], aA.x, bb3);
            fma2(acc2[1][0], aA.y, bb0); fma2(acc2[1][1], aA.y, bb1);
            fma2(acc2[1][2], aA.y, bb2); fma2(acc2[1][3], aA.y, bb3);
            fma2(acc2[2][0], aB.x, bb0); fma2(acc2[2][1], aB.x, bb1);
            fma2(acc2[2][2], aB.x, bb2); fma2(acc2[2][3], aB.x, bb3);
            fma2(acc2[3][0], aB.y, bb0); fma2(acc2[3][1], aB.y, bb1);
            fma2(acc2[3][2], aB.y, bb2); fma2(acc2[3][3], aB.y, bb3);
            fma2(acc2[4][0], aC.x, bb0); fma2(acc2[4][1], aC.x, bb1);
            fma2(acc2[4][2], aC.x, bb2); fma2(acc2[4][3], aC.x, bb3);
            fma2(acc2[5][0], aC.y, bb0); fma2(acc2[5][1], aC.y, bb1);
            fma2(acc2[5][2], aC.y, bb2); fma2(acc2[5][3], aC.y, bb3);
            fma2(acc2[6][0], aD.x, bb0); fma2(acc2[6][1], aD.x, bb1);
            fma2(acc2[6][2], aD.x, bb2); fma2(acc2[6][3], aD.x, bb3);
            fma2(acc2[7][0], aD.y, bb0); fma2(acc2[7][1], aD.y, bb1);
            fma2(acc2[7][2], aD.y, bb2); fma2(acc2[7][3], aD.y, bb3);
        }

#pragma unroll
        for (int a = 0; a < 8; a++) {
            const int ce = chan0 + 2 * a, co = ce + 1;
            const float4 ue = *(const float4*)(attn + ce * RS + colbase);
            const float4 uo = *(const float4*)(attn + co * RS + colbase);
            u64 part = 0ull;
            fma2(part, pk2(ue.x, uo.x), acc2[a][0]);
            fma2(part, pk2(ue.y, uo.y), acc2[a][1]);
            fma2(part, pk2(ue.z, uo.z), acc2[a][2]);
            fma2(part, pk2(ue.w, uo.w), acc2[a][3]);
#pragma unroll
            for (int o = 1; o < 8; o <<= 1)
                part = add2(part, (u64)__shfl_xor_sync(0xffffffffu,
                                    (unsigned long long)part, o));
            if (q == 0) {
                float pe, po;
                upk2(pe, po, part);
                fop[pt * WS + ce] = pe;
                fop[pt * WS + co] = po;
            }
        }
    }
    __syncthreads();

    // ---- phase F: preamble (combine partials) then vectorized FFN ----
    {
        const int c = tid >> 3, fpt = tid & 7;
        const int n = n0 + fpt;

        float fo = fp0[fpt * WS + c] + fp1[fpt * WS + c] + bias[c]
                 + f[((size_t)b * 64 + c) * N_ + n];
        fo = fmaxf(fo, 0.f);
        fp0[fpt * WS + c] = fo;              // fp0 becomes final fo
        __syncthreads();

        float g1 = bias[64 + c];
#pragma unroll
        for (int i4 = 0; i4 < 64; i4 += 4) {
            const float4 fv = *(const float4*)(fp0 + fpt * WS + i4);
            const float4 wv = *(const float4*)(Wf1R + c * WS + i4);
            g1 += fv.x*wv.x + fv.y*wv.y + fv.z*wv.z + fv.w*wv.w;
        }
        g1_sh[fpt * WS + c] = fmaxf(g1, 0.f);
        __syncthreads();

        float g2 = bias[128 + c];
#pragma unroll
        for (int i4 = 0; i4 < 64; i4 += 4) {
            const float4 gv = *(const float4*)(g1_sh + fpt * WS + i4);
            const float4 wv = *(const float4*)(Wf2R + c * WS + i4);
            g2 += gv.x*wv.x + gv.y*wv.y + gv.z*wv.z + gv.w*wv.w;
        }
        out_f2[((size_t)b * 64 + c) * N_ + n] =
            fmaxf(g2 + fp0[fpt * WS + c], 0.f);
    }
}

// ---------------------------------------------------------------------------
// launch
// ---------------------------------------------------------------------------
extern "C" void kernel_launch(void* const* d_in, const int* in_sizes, int n_in,
                              void* d_out, int out_size)
{
    const float* p      = (const float*)d_in[0];
    const float* f      = (const float*)d_in[1];
    const int*   idx    = (const int*)d_in[2];
    const float* W_attn = (const float*)d_in[3];
    const float* b_attn = (const float*)d_in[4];
    const float* W1     = (const float*)d_in[5];
    const float* b1     = (const float*)d_in[6];
    const float* W2     = (const float*)d_in[7];
    const float* b2     = (const float*)d_in[8];
    const float* Wf1    = (const float*)d_in[9];
    const float* bf1    = (const float*)d_in[10];
    const float* Wf2    = (const float*)d_in[11];
    const float* bf2    = (const float*)d_in[12];

    float* out = (float*)d_out;
    const int psz = B_ * N_ * 3;
    const int fsz = B_ * C_ * N_;

    float* out_f2 = out;
    if (out_size >= psz + fsz) {
        cudaMemcpyAsync(out, p, (size_t)psz * sizeof(float),
                        cudaMemcpyDeviceToDevice);
        out_f2 = out + psz;
    }

    precompute_kernel<<<dim3(N_ / 64, B_), 256>>>(f, W_attn, b_attn, W1, b1);

    cudaFuncSetAttribute(lpamlp_main_kernel,
                         cudaFuncAttributeMaxDynamicSharedMemorySize, SMEM_BYTES);
    lpamlp_main_kernel<<<dim3(N_ / 8, B_), 512, SMEM_BYTES>>>(
        p, idx, f, W_attn, W1, W2, b2, Wf1, bf1, Wf2, bf2, out_f2);
}